// round 1
// baseline (speedup 1.0000x reference)
#include <cuda_runtime.h>
#include <math.h>

// FlowLenia step: SX=SY=256, C=3, K=15, DD=5, DT=0.2, SIGMA=0.65
// out = [newA (256*256*3) | newP (256*256*15)] float32

#define NX 256
#define NC 3
#define NK 15
#define DTc 0.2f
#define SIGMAc 0.65f
#define MAc 4.35f              // DD - SIGMA
#define INV4S2 (1.0f/(4.0f*0.65f*0.65f))

static __device__ float2 g_tw[256];
static __device__ float2 g_fA[NX*NX*NC];
static __device__ float2 g_G [NX*NX*NK];
static __device__ float  g_U [NX*NX*NK];
static __device__ float  g_Uc[NX*NX*NC];
static __device__ float  g_mus[NX*NX*6];   // [x][y][d(2)][c(3)]

__global__ void tw_init_kernel() {
    int j = threadIdx.x;
    double ang = -2.0 * M_PI * (double)j / 256.0;
    double sv, cv; sincos(ang, &sv, &cv);
    g_tw[j] = make_float2((float)cv, (float)sv);
}

// In-shared 256-pt radix-2 DIT FFT. Input must be loaded bit-reversed.
// 128 threads. INV=true -> conjugate twiddles (no 1/N scaling here).
template<bool INV>
__device__ __forceinline__ void fft256(float2* s, int tid) {
#pragma unroll
    for (int m = 1; m <= 8; m++) {
        int half = 1 << (m - 1);
        int len  = half << 1;
        int g = tid >> (m - 1);
        int p = tid & (half - 1);
        int i0 = g * len + p;
        int i1 = i0 + half;
        float2 w = g_tw[p << (8 - m)];
        if (INV) w.y = -w.y;
        __syncthreads();
        float2 a = s[i0], b = s[i1];
        float2 bw = make_float2(b.x*w.x - b.y*w.y, b.x*w.y + b.y*w.x);
        s[i0] = make_float2(a.x + bw.x, a.y + bw.y);
        s[i1] = make_float2(a.x - bw.x, a.y - bw.y);
    }
    __syncthreads();
}

__device__ __forceinline__ int brev8(int i) { return (int)(__brev((unsigned)i) >> 24); }

// Forward FFT along axis1 (y) of A -> g_fA
__global__ void fftA_y(const float* __restrict__ A) {
    __shared__ float2 s[256];
    int x = blockIdx.x, c = blockIdx.y, tid = threadIdx.x;
    for (int i = tid; i < 256; i += 128)
        s[brev8(i)] = make_float2(A[(x*NX + i)*NC + c], 0.f);
    fft256<false>(s, tid);
    for (int i = tid; i < 256; i += 128)
        g_fA[(x*NX + i)*NC + c] = s[i];
}

// Forward FFT along axis0 (x) in place on g_fA
__global__ void fftA_x() {
    __shared__ float2 s[256];
    int y = blockIdx.x, c = blockIdx.y, tid = threadIdx.x;
    for (int i = tid; i < 256; i += 128)
        s[brev8(i)] = g_fA[(i*NX + y)*NC + c];
    fft256<false>(s, tid);
    for (int i = tid; i < 256; i += 128)
        g_fA[(i*NX + y)*NC + c] = s[i];
}

// G_k = fK_k * fA_{k%3}, inverse FFT along axis0 -> g_G
__global__ void mul_ifft_x(const float* __restrict__ fKr, const float* __restrict__ fKi) {
    __shared__ float2 s[256];
    int y = blockIdx.x, k = blockIdx.y, tid = threadIdx.x;
    int c = k % NC;
    for (int i = tid; i < 256; i += 128) {
        float2 a = g_fA[(i*NX + y)*NC + c];
        int idx = (i*NX + y)*NK + k;
        float kr = fKr[idx], ki = fKi[idx];
        s[brev8(i)] = make_float2(kr*a.x - ki*a.y, kr*a.y + ki*a.x);
    }
    fft256<true>(s, tid);
    for (int i = tid; i < 256; i += 128)
        g_G[(i*NX + y)*NK + k] = s[i];
}

// Inverse FFT along axis1, scale 1/65536, apply growth * P -> g_U
__global__ void ifft_y_growth(const float* __restrict__ P,
                              const float* __restrict__ mArr,
                              const float* __restrict__ sArr) {
    __shared__ float2 s[256];
    int x = blockIdx.x, k = blockIdx.y, tid = threadIdx.x;
    for (int i = tid; i < 256; i += 128)
        s[brev8(i)] = g_G[(x*NX + i)*NK + k];
    fft256<true>(s, tid);
    float mk = mArr[k], sk = sArr[k];
    float inv2s2 = 1.f / (2.f * sk * sk);
    for (int i = tid; i < 256; i += 128) {
        float u = s[i].x * (1.f / 65536.f);
        float d = u - mk;
        float gr = 2.f * expf(-d * d * inv2s2) - 1.f;
        int idx = (x*NX + i)*NK + k;
        g_U[idx] = gr * P[idx];
    }
}

// Uc[c] = sum over k with k%3==c of U[k]
__global__ void chansum() {
    int idx = blockIdx.x * blockDim.x + threadIdx.x;   // 0..65535
    const float* u = g_U + idx * NK;
#pragma unroll
    for (int c = 0; c < NC; c++)
        g_Uc[idx*NC + c] = u[c] + u[c+3] + u[c+6] + u[c+9] + u[c+12];
}

// Sobel (zero-padded SAME), flow blend, target centers mus
__global__ void sobel_mus(const float* __restrict__ A) {
    int y = blockIdx.x * blockDim.x + threadIdx.x;
    int x = blockIdx.y * blockDim.y + threadIdx.y;
    if (x >= NX || y >= NX) return;

    float uc[3][3][NC];
    float as[3][3];
#pragma unroll
    for (int di = 0; di < 3; di++) {
#pragma unroll
        for (int dj = 0; dj < 3; dj++) {
            int xi = x + di - 1, yj = y + dj - 1;
            bool in = (xi >= 0) & (xi < NX) & (yj >= 0) & (yj < NX);
            float a0 = 0.f, a1 = 0.f, a2 = 0.f;
            float u0 = 0.f, u1 = 0.f, u2 = 0.f;
            if (in) {
                int b = (xi*NX + yj);
                u0 = g_Uc[b*NC + 0]; u1 = g_Uc[b*NC + 1]; u2 = g_Uc[b*NC + 2];
                a0 = A[b*NC + 0];    a1 = A[b*NC + 1];    a2 = A[b*NC + 2];
            }
            uc[di][dj][0] = u0; uc[di][dj][1] = u1; uc[di][dj][2] = u2;
            as[di][dj] = a0 + a1 + a2;
        }
    }

    // gradient axis0: (row x+1 with weights 1,2,1 over y) - (row x-1)
    float cg0 = (as[2][0] + 2.f*as[2][1] + as[2][2]) - (as[0][0] + 2.f*as[0][1] + as[0][2]);
    // gradient axis1: (col y+1) - (col y-1)
    float cg1 = (as[0][2] + 2.f*as[1][2] + as[2][2]) - (as[0][0] + 2.f*as[1][0] + as[2][0]);

    int b = (x*NX + y);
    float p0 = (float)x + 0.5f, p1 = (float)y + 0.5f;
#pragma unroll
    for (int c = 0; c < NC; c++) {
        float f0 = (uc[2][0][c] + 2.f*uc[2][1][c] + uc[2][2][c])
                 - (uc[0][0][c] + 2.f*uc[0][1][c] + uc[0][2][c]);
        float f1 = (uc[0][2][c] + 2.f*uc[1][2][c] + uc[2][2][c])
                 - (uc[0][0][c] + 2.f*uc[1][0][c] + uc[2][0][c]);
        float ac = A[b*NC + c] * 0.5f;
        float alpha = fminf(ac * ac, 1.f);
        float F0 = fminf(fmaxf(f0 * (1.f - alpha) - cg0 * alpha, -MAc), MAc);
        float F1 = fminf(fmaxf(f1 * (1.f - alpha) - cg1 * alpha, -MAc), MAc);
        float mu0 = fminf(fmaxf(p0 + DTc * F0, SIGMAc), (float)NX - SIGMAc);
        float mu1 = fminf(fmaxf(p1 + DTc * F1, SIGMAc), (float)NX - SIGMAc);
        g_mus[b*6 + 0*3 + c] = mu0;
        g_mus[b*6 + 1*3 + c] = mu1;
    }
}

// Reintegration: only |shift|<=2 can contribute (area support 0.5+sigma=1.15,
// |DT*F|<=0.87 => |shift|<2.02); farther shifts give exactly-zero area AND
// exactly-zero softmax weight, so 5x5 gather == reference 11x11.
__global__ void reint(const float* __restrict__ A, const float* __restrict__ P,
                      float* __restrict__ outA, float* __restrict__ outP) {
    int y = blockIdx.x * blockDim.x + threadIdx.x;
    int x = blockIdx.y * blockDim.y + threadIdx.y;
    if (x >= NX || y >= NX) return;

    float accA[NC] = {0.f, 0.f, 0.f};
    float accP[NK];
#pragma unroll
    for (int k = 0; k < NK; k++) accP[k] = 0.f;
    float accW = 0.f;
    float p0 = (float)x + 0.5f, p1 = (float)y + 0.5f;

#pragma unroll
    for (int dx = -2; dx <= 2; dx++) {
#pragma unroll
        for (int dy = -2; dy <= 2; dy++) {
            int xs = (x - dx) & 255;
            int ys = (y - dy) & 255;
            int b = xs*NX + ys;
            const float* mu = g_mus + b*6;
            const float* Ar = A + b*3;
            float suma = 0.f;
#pragma unroll
            for (int c = 0; c < NC; c++) {
                float d0 = fabsf(p0 - mu[c]);
                float d1 = fabsf(p1 - mu[3 + c]);
                float s0 = fminf(fmaxf(0.5f + SIGMAc - d0, 0.f), 1.f);
                float s1 = fminf(fmaxf(0.5f + SIGMAc - d1, 0.f), 1.f);
                float area = s0 * s1 * INV4S2;
                float v = Ar[c] * area;
                accA[c] += v;
                suma += v;
            }
            if (suma > 0.f) {
                float w = expf(suma) - 1.f;
                accW += w;
                const float* Pr = P + b*NK;
#pragma unroll
                for (int k = 0; k < NK; k++) accP[k] += Pr[k] * w;
            }
        }
    }

    int o = x*NX + y;
#pragma unroll
    for (int c = 0; c < NC; c++) outA[o*NC + c] = accA[c];
    float inv = 1.f / (accW + 1e-10f);
#pragma unroll
    for (int k = 0; k < NK; k++) outP[o*NK + k] = accP[k] * inv;
}

extern "C" void kernel_launch(void* const* d_in, const int* in_sizes, int n_in,
                              void* d_out, int out_size) {
    const float* A   = (const float*)d_in[0];
    const float* P   = (const float*)d_in[1];
    const float* fKr = (const float*)d_in[2];
    const float* fKi = (const float*)d_in[3];
    const float* m   = (const float*)d_in[4];
    const float* s   = (const float*)d_in[5];
    float* outA = (float*)d_out;
    float* outP = outA + NX*NX*NC;

    tw_init_kernel<<<1, 256>>>();
    fftA_y      <<<dim3(NX, NC), 128>>>(A);
    fftA_x      <<<dim3(NX, NC), 128>>>();
    mul_ifft_x  <<<dim3(NX, NK), 128>>>(fKr, fKi);
    ifft_y_growth<<<dim3(NX, NK), 128>>>(P, m, s);
    chansum     <<<NX, 256>>>();
    sobel_mus   <<<dim3(16, 16), dim3(16, 16)>>>(A);
    reint       <<<dim3(16, 16), dim3(16, 16)>>>(A, P, outA, outP);
}

// round 2
// speedup vs baseline: 1.3391x; 1.3391x over previous
#include <cuda_runtime.h>
#include <math.h>

// FlowLenia step: SX=SY=256, C=3, K=15, DD=5, DT=0.2, SIGMA=0.65
// out = [newA (256*256*3) | newP (256*256*15)] float32

#define NX 256
#define NC 3
#define NK 15
#define NP 8                    // ceil(15/2) packed real pairs
#define DTc 0.2f
#define SIGMAc 0.65f
#define MAc 4.35f               // DD - SIGMA
#define INV4S2 (1.0f/(4.0f*0.65f*0.65f))
#define SPAD 272                // 256 + 16 skew pad
#define IDX(i) ((i) + ((i) >> 4))

static __device__ float2 g_tw[256];
static __device__ float2 g_fA[NX*NX*NC];
static __device__ float2 g_G [NX*NX*NP];
static __device__ float  g_U [NX*NX*NK];
static __device__ float  g_Uc[NX*NX*NC];
static __device__ float  g_mus[NX*NX*6];   // [x][y][d(2)][c(3)]

__global__ void tw_init_kernel() {
    int j = threadIdx.x;
    double ang = -2.0 * M_PI * (double)j / 256.0;
    double sv, cv; sincos(ang, &sv, &cv);
    g_tw[j] = make_float2((float)cv, (float)sv);
}

__device__ __forceinline__ int rev4(int i) {
    // reverse 4 base-4 digits of an 8-bit index
    return ((i & 3) << 6) | ((i & 0xC) << 2) | ((i >> 2) & 0xC) | ((i >> 6) & 3);
}

__device__ __forceinline__ float2 cmul(float2 a, float2 b) {
    return make_float2(a.x*b.x - a.y*b.y, a.x*b.y + a.y*b.x);
}

// In-shared 256-pt radix-4 DIT FFT, 64 threads per FFT.
// Input must be loaded base-4 digit-reversed via IDX(). Bank-skewed smem.
template<bool INV>
__device__ __forceinline__ void fft256_r4(float2* s, int t) {
#pragma unroll
    for (int m = 0; m < 4; m++) {
        int q    = 1 << (2*m);           // 1,4,16,64
        int p    = t & (q - 1);
        int grp  = t >> (2*m);
        int base = grp*(q << 2) + p;
        int ts   = 64 >> (2*m);          // 256/(4q)
        float2 w1 = g_tw[p*ts];
        float2 w2 = g_tw[2*p*ts];
        float2 w3 = g_tw[3*p*ts];
        if (INV) { w1.y = -w1.y; w2.y = -w2.y; w3.y = -w3.y; }
        __syncthreads();
        float2 x0 = s[IDX(base)];
        float2 t1 = cmul(s[IDX(base +   q)], w1);
        float2 t2 = cmul(s[IDX(base + 2*q)], w2);
        float2 t3 = cmul(s[IDX(base + 3*q)], w3);
        float2 b0 = make_float2(x0.x + t2.x, x0.y + t2.y);
        float2 b1 = make_float2(x0.x - t2.x, x0.y - t2.y);
        float2 b2 = make_float2(t1.x + t3.x, t1.y + t3.y);
        float2 b3 = make_float2(t1.x - t3.x, t1.y - t3.y);
        float2 ib3 = INV ? make_float2(-b3.y, b3.x) : make_float2(b3.y, -b3.x);
        s[IDX(base)]        = make_float2(b0.x + b2.x, b0.y + b2.y);
        s[IDX(base +   q)]  = make_float2(b1.x + ib3.x, b1.y + ib3.y);
        s[IDX(base + 2*q)]  = make_float2(b0.x - b2.x, b0.y - b2.y);
        s[IDX(base + 3*q)]  = make_float2(b1.x - ib3.x, b1.y - ib3.y);
    }
    __syncthreads();
}

// Forward FFT along axis1 (y): one block = one row x, 3 channels in y-lanes
__global__ void fftA_y(const float* __restrict__ A) {
    __shared__ float2 sm[NC][SPAD];
    int x = blockIdx.x, c = threadIdx.y, t = threadIdx.x;
    float2* s = sm[c];
#pragma unroll
    for (int jj = 0; jj < 4; jj++) {
        int i = t + 64*jj;
        s[IDX(rev4(i))] = make_float2(A[(x*NX + i)*NC + c], 0.f);
    }
    fft256_r4<false>(s, t);
#pragma unroll
    for (int jj = 0; jj < 4; jj++) {
        int i = t + 64*jj;
        g_fA[(x*NX + i)*NC + c] = s[IDX(i)];
    }
}

// Forward FFT along axis0 (x), in place on g_fA
__global__ void fftA_x() {
    __shared__ float2 sm[NC][SPAD];
    int y = blockIdx.x, c = threadIdx.y, t = threadIdx.x;
    float2* s = sm[c];
#pragma unroll
    for (int jj = 0; jj < 4; jj++) {
        int i = t + 64*jj;
        s[IDX(rev4(i))] = g_fA[(i*NX + y)*NC + c];
    }
    fft256_r4<false>(s, t);
#pragma unroll
    for (int jj = 0; jj < 4; jj++) {
        int i = t + 64*jj;
        g_fA[(i*NX + y)*NC + c] = s[IDX(i)];
    }
}

// Packed pair j: H = fK_{2j}*fA_{c1} + i * fK_{2j+1}*fA_{c2}; inverse FFT along x.
// Valid because Re(ifft2(G_k)) is the real field U_k, so ifft2(G1 + i G2) = U1 + i U2.
__global__ void mul_ifft_x_pair(const float* __restrict__ fKr, const float* __restrict__ fKi) {
    __shared__ float2 sm[2][SPAD];
    int y = blockIdx.x, t = threadIdx.x;
    int j = blockIdx.y * 2 + threadIdx.y;          // pair index 0..7
    float2* s = sm[threadIdx.y];
    int k1 = 2*j, k2 = 2*j + 1;
    int c1 = k1 % NC, c2 = k2 % NC;
#pragma unroll
    for (int jj = 0; jj < 4; jj++) {
        int i = t + 64*jj;
        int rowb = i*NX + y;
        float2 a1 = g_fA[rowb*NC + c1];
        int i1 = rowb*NK + k1;
        float kr = fKr[i1], ki = fKi[i1];
        float2 z = make_float2(kr*a1.x - ki*a1.y, kr*a1.y + ki*a1.x);
        if (k2 < NK) {
            float2 a2 = g_fA[rowb*NC + c2];
            int i2 = rowb*NK + k2;
            float kr2 = fKr[i2], ki2 = fKi[i2];
            float zr = kr2*a2.x - ki2*a2.y;
            float zi = kr2*a2.y + ki2*a2.x;
            z.x -= zi; z.y += zr;                  // + i*(zr + i*zi)
        }
        s[IDX(rev4(i))] = z;
    }
    fft256_r4<true>(s, t);
#pragma unroll
    for (int jj = 0; jj < 4; jj++) {
        int i = t + 64*jj;
        g_G[(i*NX + y)*NP + j] = s[IDX(i)];
    }
}

// Inverse FFT along y for packed pair, unpack real/imag -> U_{k1}, U_{k2}, growth*P
__global__ void ifft_y_growth_pair(const float* __restrict__ P,
                                   const float* __restrict__ mArr,
                                   const float* __restrict__ sArr) {
    __shared__ float2 sm[2][SPAD];
    int x = blockIdx.x, t = threadIdx.x;
    int j = blockIdx.y * 2 + threadIdx.y;
    float2* s = sm[threadIdx.y];
#pragma unroll
    for (int jj = 0; jj < 4; jj++) {
        int i = t + 64*jj;
        s[IDX(rev4(i))] = g_G[(x*NX + i)*NP + j];
    }
    fft256_r4<true>(s, t);
    int k1 = 2*j, k2 = 2*j + 1;
    float m1 = mArr[k1], s1 = sArr[k1];
    float inv1 = 1.f / (2.f * s1 * s1);
    float m2 = 0.f, inv2 = 0.f;
    if (k2 < NK) { m2 = mArr[k2]; float s2 = sArr[k2]; inv2 = 1.f / (2.f * s2 * s2); }
#pragma unroll
    for (int jj = 0; jj < 4; jj++) {
        int i = t + 64*jj;
        float2 v = s[IDX(i)];
        int b = (x*NX + i)*NK;
        float u1 = v.x * (1.f / 65536.f);
        float d1 = u1 - m1;
        g_U[b + k1] = (2.f * expf(-d1*d1*inv1) - 1.f) * P[b + k1];
        if (k2 < NK) {
            float u2 = v.y * (1.f / 65536.f);
            float d2 = u2 - m2;
            g_U[b + k2] = (2.f * expf(-d2*d2*inv2) - 1.f) * P[b + k2];
        }
    }
}

// Uc[c] = sum over k with k%3==c of U[k]
__global__ void chansum() {
    int idx = blockIdx.x * blockDim.x + threadIdx.x;   // 0..65535
    const float* u = g_U + idx * NK;
#pragma unroll
    for (int c = 0; c < NC; c++)
        g_Uc[idx*NC + c] = u[c] + u[c+3] + u[c+6] + u[c+9] + u[c+12];
}

// Sobel (zero-padded SAME), flow blend, target centers mus
__global__ void sobel_mus(const float* __restrict__ A) {
    int y = blockIdx.x * blockDim.x + threadIdx.x;
    int x = blockIdx.y * blockDim.y + threadIdx.y;
    if (x >= NX || y >= NX) return;

    float uc[3][3][NC];
    float as[3][3];
#pragma unroll
    for (int di = 0; di < 3; di++) {
#pragma unroll
        for (int dj = 0; dj < 3; dj++) {
            int xi = x + di - 1, yj = y + dj - 1;
            bool in = (xi >= 0) & (xi < NX) & (yj >= 0) & (yj < NX);
            float a0 = 0.f, a1 = 0.f, a2 = 0.f;
            float u0 = 0.f, u1 = 0.f, u2 = 0.f;
            if (in) {
                int b = (xi*NX + yj);
                u0 = g_Uc[b*NC + 0]; u1 = g_Uc[b*NC + 1]; u2 = g_Uc[b*NC + 2];
                a0 = A[b*NC + 0];    a1 = A[b*NC + 1];    a2 = A[b*NC + 2];
            }
            uc[di][dj][0] = u0; uc[di][dj][1] = u1; uc[di][dj][2] = u2;
            as[di][dj] = a0 + a1 + a2;
        }
    }

    float cg0 = (as[2][0] + 2.f*as[2][1] + as[2][2]) - (as[0][0] + 2.f*as[0][1] + as[0][2]);
    float cg1 = (as[0][2] + 2.f*as[1][2] + as[2][2]) - (as[0][0] + 2.f*as[1][0] + as[2][0]);

    int b = (x*NX + y);
    float p0 = (float)x + 0.5f, p1 = (float)y + 0.5f;
#pragma unroll
    for (int c = 0; c < NC; c++) {
        float f0 = (uc[2][0][c] + 2.f*uc[2][1][c] + uc[2][2][c])
                 - (uc[0][0][c] + 2.f*uc[0][1][c] + uc[0][2][c]);
        float f1 = (uc[0][2][c] + 2.f*uc[1][2][c] + uc[2][2][c])
                 - (uc[0][0][c] + 2.f*uc[1][0][c] + uc[2][0][c]);
        float ac = A[b*NC + c] * 0.5f;
        float alpha = fminf(ac * ac, 1.f);
        float F0 = fminf(fmaxf(f0 * (1.f - alpha) - cg0 * alpha, -MAc), MAc);
        float F1 = fminf(fmaxf(f1 * (1.f - alpha) - cg1 * alpha, -MAc), MAc);
        float mu0 = fminf(fmaxf(p0 + DTc * F0, SIGMAc), (float)NX - SIGMAc);
        float mu1 = fminf(fmaxf(p1 + DTc * F1, SIGMAc), (float)NX - SIGMAc);
        g_mus[b*6 + 0*3 + c] = mu0;
        g_mus[b*6 + 1*3 + c] = mu1;
    }
}

// Reintegration: only |shift|<=2 contributes (support 0.5+sigma=1.15, |DT*F|<=0.87);
// farther shifts give exactly-zero area AND exactly-zero softmax weight.
__global__ void reint(const float* __restrict__ A, const float* __restrict__ P,
                      float* __restrict__ outA, float* __restrict__ outP) {
    int y = blockIdx.x * blockDim.x + threadIdx.x;
    int x = blockIdx.y * blockDim.y + threadIdx.y;
    if (x >= NX || y >= NX) return;

    float accA[NC] = {0.f, 0.f, 0.f};
    float accP[NK];
#pragma unroll
    for (int k = 0; k < NK; k++) accP[k] = 0.f;
    float accW = 0.f;
    float p0 = (float)x + 0.5f, p1 = (float)y + 0.5f;

#pragma unroll
    for (int dx = -2; dx <= 2; dx++) {
#pragma unroll
        for (int dy = -2; dy <= 2; dy++) {
            int xs = (x - dx) & 255;
            int ys = (y - dy) & 255;
            int b = xs*NX + ys;
            const float* mu = g_mus + b*6;
            const float* Ar = A + b*3;
            float suma = 0.f;
#pragma unroll
            for (int c = 0; c < NC; c++) {
                float d0 = fabsf(p0 - mu[c]);
                float d1 = fabsf(p1 - mu[3 + c]);
                float s0 = fminf(fmaxf(0.5f + SIGMAc - d0, 0.f), 1.f);
                float s1 = fminf(fmaxf(0.5f + SIGMAc - d1, 0.f), 1.f);
                float area = s0 * s1 * INV4S2;
                float v = Ar[c] * area;
                accA[c] += v;
                suma += v;
            }
            if (suma > 0.f) {
                float w = expf(suma) - 1.f;
                accW += w;
                const float* Pr = P + b*NK;
#pragma unroll
                for (int k = 0; k < NK; k++) accP[k] += Pr[k] * w;
            }
        }
    }

    int o = x*NX + y;
#pragma unroll
    for (int c = 0; c < NC; c++) outA[o*NC + c] = accA[c];
    float inv = 1.f / (accW + 1e-10f);
#pragma unroll
    for (int k = 0; k < NK; k++) outP[o*NK + k] = accP[k] * inv;
}

extern "C" void kernel_launch(void* const* d_in, const int* in_sizes, int n_in,
                              void* d_out, int out_size) {
    const float* A   = (const float*)d_in[0];
    const float* P   = (const float*)d_in[1];
    const float* fKr = (const float*)d_in[2];
    const float* fKi = (const float*)d_in[3];
    const float* m   = (const float*)d_in[4];
    const float* s   = (const float*)d_in[5];
    float* outA = (float*)d_out;
    float* outP = outA + NX*NX*NC;

    tw_init_kernel    <<<1, 256>>>();
    fftA_y            <<<NX, dim3(64, NC)>>>(A);
    fftA_x            <<<NX, dim3(64, NC)>>>();
    mul_ifft_x_pair   <<<dim3(NX, 4), dim3(64, 2)>>>(fKr, fKi);
    ifft_y_growth_pair<<<dim3(NX, 4), dim3(64, 2)>>>(P, m, s);
    chansum           <<<NX, 256>>>();
    sobel_mus         <<<dim3(16, 16), dim3(16, 16)>>>(A);
    reint             <<<dim3(16, 16), dim3(16, 16)>>>(A, P, outA, outP);
}

// round 3
// speedup vs baseline: 1.6131x; 1.2046x over previous
#include <cuda_runtime.h>
#include <math.h>

// FlowLenia step: SX=SY=256, C=3, K=15, DD=5, DT=0.2, SIGMA=0.65
// out = [newA (256*256*3) | newP (256*256*15)] float32

#define NX 256
#define NC 3
#define NK 15
#define NP 8                    // ceil(15/2) packed real pairs
#define DTc 0.2f
#define SIGMAc 0.65f
#define MAc 4.35f               // DD - SIGMA
#define INV4S2 (1.0f/(4.0f*0.65f*0.65f))
#define IDX(i) ((i) + ((i) >> 4))   // skew pad, max 271
#define FSTR 273                    // float2 stride per FFT buffer (bank-stagger)

static __device__ float2 g_tw[256];
static __device__ float2 g_fA[NC*NX*NX];     // [c][x][y] planar complex
static __device__ float2 g_G [NX*NX*NP];     // [x][y][j]  8 pairs contiguous
static __device__ float  g_Uc[NX*NX*NC];     // [y][x][c]
static __device__ float  g_mus[NX*NX*6];     // [x][y][d(2)][c(3)]

__global__ void tw_init_kernel() {
    int j = threadIdx.x;
    double ang = -2.0 * M_PI * (double)j / 256.0;
    double sv, cv; sincos(ang, &sv, &cv);
    g_tw[j] = make_float2((float)cv, (float)sv);
}

__device__ __forceinline__ int rev4(int i) {
    return ((i & 3) << 6) | ((i & 0xC) << 2) | ((i >> 2) & 0xC) | ((i >> 6) & 3);
}
__device__ __forceinline__ float2 cmul(float2 a, float2 b) {
    return make_float2(a.x*b.x - a.y*b.y, a.x*b.y + a.y*b.x);
}

// In-shared 256-pt radix-4 DIT FFT, 64 threads per FFT, input digit-reversed via IDX.
// Starts with __syncthreads (covers producer writes), ends with __syncthreads.
template<bool INV>
__device__ __forceinline__ void fft256_r4(float2* s, int t) {
#pragma unroll
    for (int m = 0; m < 4; m++) {
        int q    = 1 << (2*m);
        int p    = t & (q - 1);
        int grp  = t >> (2*m);
        int base = grp*(q << 2) + p;
        int ts   = 64 >> (2*m);
        float2 w1 = g_tw[p*ts];
        float2 w2 = g_tw[2*p*ts];
        float2 w3 = g_tw[3*p*ts];
        if (INV) { w1.y = -w1.y; w2.y = -w2.y; w3.y = -w3.y; }
        __syncthreads();
        float2 x0 = s[IDX(base)];
        float2 t1 = cmul(s[IDX(base +   q)], w1);
        float2 t2 = cmul(s[IDX(base + 2*q)], w2);
        float2 t3 = cmul(s[IDX(base + 3*q)], w3);
        float2 b0 = make_float2(x0.x + t2.x, x0.y + t2.y);
        float2 b1 = make_float2(x0.x - t2.x, x0.y - t2.y);
        float2 b2 = make_float2(t1.x + t3.x, t1.y + t3.y);
        float2 b3 = make_float2(t1.x - t3.x, t1.y - t3.y);
        float2 ib3 = INV ? make_float2(-b3.y, b3.x) : make_float2(b3.y, -b3.x);
        s[IDX(base)]        = make_float2(b0.x + b2.x, b0.y + b2.y);
        s[IDX(base +   q)]  = make_float2(b1.x + ib3.x, b1.y + ib3.y);
        s[IDX(base + 2*q)]  = make_float2(b0.x - b2.x, b0.y - b2.y);
        s[IDX(base + 3*q)]  = make_float2(b1.x - ib3.x, b1.y - ib3.y);
    }
    __syncthreads();
}

// S1: FFT along y. block = one row x, 3 channels. Write planar [c][x][y] (coalesced).
__global__ void s1_fft_y(const float* __restrict__ A) {
    __shared__ float2 sm[NC][FSTR];
    int x = blockIdx.x, c = threadIdx.y, t = threadIdx.x;
    float2* s = sm[c];
#pragma unroll
    for (int jj = 0; jj < 4; jj++) {
        int i = t + 64*jj;
        s[IDX(rev4(i))] = make_float2(A[(x*NX + i)*NC + c], 0.f);
    }
    fft256_r4<false>(s, t);
#pragma unroll
    for (int jj = 0; jj < 4; jj++) {
        int i = t + 64*jj;
        g_fA[c*NX*NX + x*NX + i] = s[IDX(i)];
    }
}

// S2: FFT along x, tiled: block = 8 ky-columns of one channel, cooperative 64B loads.
__global__ void s2_fft_x() {
    __shared__ float2 sm[8][FSTR];
    int c = blockIdx.y, y0 = blockIdx.x * 8;
    int t = threadIdx.x, yl = threadIdx.y;
    int tid = yl*64 + t;
    int base = c*NX*NX;
    for (int e = tid; e < 2048; e += 512) {
        int x = e >> 3, yy = e & 7;
        sm[yy][IDX(rev4(x))] = g_fA[base + x*NX + y0 + yy];
    }
    fft256_r4<false>(sm[yl], t);
    for (int e = tid; e < 2048; e += 512) {
        int x = e >> 3, yy = e & 7;
        g_fA[base + x*NX + y0 + yy] = sm[yy][IDX(x)];
    }
}

// S3: multiply by fK + inverse FFT along y. block = one kx row, 8 packed pairs.
// H_j = fK_{2j}*fA_{c1} + i*fK_{2j+1}*fA_{c2}; Re/Im of ifft2 give U_{2j}, U_{2j+1}.
// fK reads are dense (all k,y for this x consumed here).
__global__ void s3_mul_ifft_y(const float* __restrict__ fKr, const float* __restrict__ fKi) {
    __shared__ float2 sm[NP][FSTR];
    __shared__ float2 sfA[NC][NX];
    int x = blockIdx.x, t = threadIdx.x, j = threadIdx.y;
    int tid = j*64 + t;
    for (int e = tid; e < NC*NX; e += 512) {
        int c = e >> 8, y = e & 255;
        sfA[c][y] = g_fA[c*NX*NX + x*NX + y];
    }
    __syncthreads();
    for (int e = tid; e < 2048; e += 512) {
        int y = e >> 3, jj = e & 7;
        int k1 = 2*jj;
        int idx = (x*NX + y)*NK;
        float2 a1 = sfA[k1 % NC][y];
        float kr = fKr[idx + k1], ki = fKi[idx + k1];
        float2 H = make_float2(kr*a1.x - ki*a1.y, kr*a1.y + ki*a1.x);
        if (k1 + 1 < NK) {
            float2 a2 = sfA[(k1+1) % NC][y];
            float kr2 = fKr[idx + k1 + 1], ki2 = fKi[idx + k1 + 1];
            float zr = kr2*a2.x - ki2*a2.y;
            float zi = kr2*a2.y + ki2*a2.x;
            H.x -= zi; H.y += zr;
        }
        sm[jj][IDX(rev4(y))] = H;
    }
    fft256_r4<true>(sm[j], t);
    for (int e = tid; e < 2048; e += 512) {
        int y = e >> 3, jj = e & 7;
        g_G[(x*NX + y)*NP + jj] = sm[jj][IDX(y)];
    }
}

// S4: inverse FFT along x + growth*P + channel-sum, fused. block = one y, 8 pairs.
// Eliminates g_U roundtrip and chansum kernel.
__global__ void s4_ifft_x_growth(const float* __restrict__ P,
                                 const float* __restrict__ mArr,
                                 const float* __restrict__ sArr) {
    __shared__ float2 sm[NP][FSTR];
    __shared__ float  sP[NX*17];     // P tile, then growth*P in place; pad 17 (CF)
    int y = blockIdx.x, t = threadIdx.x, j = threadIdx.y;
    int tid = j*64 + t;
    for (int e = tid; e < 2048; e += 512) {
        int xx = e >> 3, jj = e & 7;
        sm[jj][IDX(rev4(xx))] = g_G[(xx*NX + y)*NP + jj];
    }
    for (int e = tid; e < NX*NK; e += 512) {
        int xx = e / NK, k = e - xx*NK;
        sP[xx*17 + k] = P[(xx*NX + y)*NK + k];
    }
    fft256_r4<true>(sm[j], t);        // internal syncs also order the sP loads

    int k1 = 2*j, k2 = 2*j + 1;
    float m1 = mArr[k1], s1 = sArr[k1];
    float inv1 = 1.f / (2.f * s1 * s1);
    float m2 = 0.f, inv2 = 0.f;
    if (k2 < NK) { m2 = mArr[k2]; float s2 = sArr[k2]; inv2 = 1.f / (2.f * s2 * s2); }
#pragma unroll
    for (int jj2 = 0; jj2 < 4; jj2++) {
        int xx = t + 64*jj2;
        float2 v = sm[j][IDX(xx)];
        float u1 = v.x * (1.f / 65536.f);
        float d1 = u1 - m1;
        sP[xx*17 + k1] *= (2.f * expf(-d1*d1*inv1) - 1.f);
        if (k2 < NK) {
            float u2 = v.y * (1.f / 65536.f);
            float d2 = u2 - m2;
            sP[xx*17 + k2] *= (2.f * expf(-d2*d2*inv2) - 1.f);
        }
    }
    __syncthreads();
    for (int e = tid; e < NX*NC; e += 512) {
        int xx = e / NC, c = e - xx*NC;
        const float* u = sP + xx*17;
        g_Uc[(y*NX + xx)*NC + c] = u[c] + u[c+3] + u[c+6] + u[c+9] + u[c+12];
    }
}

// Sobel (zero-padded SAME), flow blend, target centers mus. Uc is [y][x][c].
__global__ void sobel_mus(const float* __restrict__ A) {
    int y = blockIdx.x * blockDim.x + threadIdx.x;
    int x = blockIdx.y * blockDim.y + threadIdx.y;
    if (x >= NX || y >= NX) return;

    float uc[3][3][NC];
    float as[3][3];
#pragma unroll
    for (int di = 0; di < 3; di++) {
#pragma unroll
        for (int dj = 0; dj < 3; dj++) {
            int xi = x + di - 1, yj = y + dj - 1;
            bool in = (xi >= 0) & (xi < NX) & (yj >= 0) & (yj < NX);
            float a0 = 0.f, a1 = 0.f, a2 = 0.f;
            float u0 = 0.f, u1 = 0.f, u2 = 0.f;
            if (in) {
                int bA = (xi*NX + yj);
                int bU = (yj*NX + xi);
                u0 = g_Uc[bU*NC + 0]; u1 = g_Uc[bU*NC + 1]; u2 = g_Uc[bU*NC + 2];
                a0 = A[bA*NC + 0];    a1 = A[bA*NC + 1];    a2 = A[bA*NC + 2];
            }
            uc[di][dj][0] = u0; uc[di][dj][1] = u1; uc[di][dj][2] = u2;
            as[di][dj] = a0 + a1 + a2;
        }
    }

    float cg0 = (as[2][0] + 2.f*as[2][1] + as[2][2]) - (as[0][0] + 2.f*as[0][1] + as[0][2]);
    float cg1 = (as[0][2] + 2.f*as[1][2] + as[2][2]) - (as[0][0] + 2.f*as[1][0] + as[2][0]);

    int b = (x*NX + y);
    float p0 = (float)x + 0.5f, p1 = (float)y + 0.5f;
#pragma unroll
    for (int c = 0; c < NC; c++) {
        float f0 = (uc[2][0][c] + 2.f*uc[2][1][c] + uc[2][2][c])
                 - (uc[0][0][c] + 2.f*uc[0][1][c] + uc[0][2][c]);
        float f1 = (uc[0][2][c] + 2.f*uc[1][2][c] + uc[2][2][c])
                 - (uc[0][0][c] + 2.f*uc[1][0][c] + uc[2][0][c]);
        float ac = A[b*NC + c] * 0.5f;
        float alpha = fminf(ac * ac, 1.f);
        float F0 = fminf(fmaxf(f0 * (1.f - alpha) - cg0 * alpha, -MAc), MAc);
        float F1 = fminf(fmaxf(f1 * (1.f - alpha) - cg1 * alpha, -MAc), MAc);
        g_mus[b*6 + 0*3 + c] = fminf(fmaxf(p0 + DTc * F0, SIGMAc), (float)NX - SIGMAc);
        g_mus[b*6 + 1*3 + c] = fminf(fmaxf(p1 + DTc * F1, SIGMAc), (float)NX - SIGMAc);
    }
}

// Reintegration: only |shift|<=2 contributes (support 0.5+sigma=1.15, |DT*F|<=0.87);
// farther shifts give exactly-zero area AND exactly-zero softmax weight.
__global__ void reint(const float* __restrict__ A, const float* __restrict__ P,
                      float* __restrict__ outA, float* __restrict__ outP) {
    int y = blockIdx.x * blockDim.x + threadIdx.x;
    int x = blockIdx.y * blockDim.y + threadIdx.y;
    if (x >= NX || y >= NX) return;

    float accA[NC] = {0.f, 0.f, 0.f};
    float accP[NK];
#pragma unroll
    for (int k = 0; k < NK; k++) accP[k] = 0.f;
    float accW = 0.f;
    float p0 = (float)x + 0.5f, p1 = (float)y + 0.5f;

#pragma unroll
    for (int dx = -2; dx <= 2; dx++) {
#pragma unroll
        for (int dy = -2; dy <= 2; dy++) {
            int xs = (x - dx) & 255;
            int ys = (y - dy) & 255;
            int b = xs*NX + ys;
            const float* mu = g_mus + b*6;
            const float* Ar = A + b*3;
            float suma = 0.f;
#pragma unroll
            for (int c = 0; c < NC; c++) {
                float d0 = fabsf(p0 - mu[c]);
                float d1 = fabsf(p1 - mu[3 + c]);
                float s0 = fminf(fmaxf(0.5f + SIGMAc - d0, 0.f), 1.f);
                float s1 = fminf(fmaxf(0.5f + SIGMAc - d1, 0.f), 1.f);
                float v = Ar[c] * (s0 * s1 * INV4S2);
                accA[c] += v;
                suma += v;
            }
            if (suma > 0.f) {
                float w = expf(suma) - 1.f;
                accW += w;
                const float* Pr = P + b*NK;
#pragma unroll
                for (int k = 0; k < NK; k++) accP[k] += Pr[k] * w;
            }
        }
    }

    int o = x*NX + y;
#pragma unroll
    for (int c = 0; c < NC; c++) outA[o*NC + c] = accA[c];
    float inv = 1.f / (accW + 1e-10f);
#pragma unroll
    for (int k = 0; k < NK; k++) outP[o*NK + k] = accP[k] * inv;
}

extern "C" void kernel_launch(void* const* d_in, const int* in_sizes, int n_in,
                              void* d_out, int out_size) {
    const float* A   = (const float*)d_in[0];
    const float* P   = (const float*)d_in[1];
    const float* fKr = (const float*)d_in[2];
    const float* fKi = (const float*)d_in[3];
    const float* m   = (const float*)d_in[4];
    const float* s   = (const float*)d_in[5];
    float* outA = (float*)d_out;
    float* outP = outA + NX*NX*NC;

    tw_init_kernel   <<<1, 256>>>();
    s1_fft_y         <<<NX, dim3(64, NC)>>>(A);
    s2_fft_x         <<<dim3(32, NC), dim3(64, 8)>>>();
    s3_mul_ifft_y    <<<NX, dim3(64, NP)>>>(fKr, fKi);
    s4_ifft_x_growth <<<NX, dim3(64, NP)>>>(P, m, s);
    sobel_mus        <<<dim3(16, 16), dim3(16, 16)>>>(A);
    reint            <<<dim3(16, 16), dim3(16, 16)>>>(A, P, outA, outP);
}

// round 4
// speedup vs baseline: 1.9772x; 1.2257x over previous
#include <cuda_runtime.h>
#include <math.h>

// FlowLenia step: SX=SY=256, C=3, K=15, DD=5, DT=0.2, SIGMA=0.65
// out = [newA (256*256*3) | newP (256*256*15)] float32

#define NX 256
#define NC 3
#define NK 15
#define NP 8                    // ceil(15/2) packed real pairs
#define DTc 0.2f
#define SIGMAc 0.65f
#define MAc 4.35f               // DD - SIGMA
#define INV4S2 (1.0f/(4.0f*0.65f*0.65f))
#define SUPP 1.15f              // 0.5 + SIGMA
#define IDX(i) ((i) + ((i) >> 4))   // skew pad, max 271
#define FSTR 273                    // float2 stride per FFT buffer

static __device__ float2 g_fA[NC*NX*NX];     // [c][x][y] planar complex
static __device__ float2 g_G [NX*NX*NP];     // [x][y][j]  8 pairs contiguous
static __device__ float  g_Uc[NX*NX*NC];     // [y][x][c]

__device__ __forceinline__ int rev4(int i) {
    return ((i & 3) << 6) | ((i & 0xC) << 2) | ((i >> 2) & 0xC) | ((i >> 6) & 3);
}
__device__ __forceinline__ float2 cmul(float2 a, float2 b) {
    return make_float2(a.x*b.x - a.y*b.y, a.x*b.y + a.y*b.x);
}

// Per-block twiddle table in smem: tw[j] = exp(-2*pi*i*j/256), sincospif 1-ulp.
__device__ __forceinline__ void tw_init_smem(float2* tw, int tid, int nthr) {
    for (int j = tid; j < 256; j += nthr) {
        float sv, cv;
        sincospif(-(float)j * (1.0f/128.0f), &sv, &cv);
        tw[j] = make_float2(cv, sv);
    }
}

// In-shared 256-pt radix-4 DIT FFT, 64 threads per FFT, input digit-reversed via IDX.
// Syncs at top of each stage (covers producer writes incl. tw table); final sync at end.
template<bool INV>
__device__ __forceinline__ void fft256_r4(float2* s, const float2* tw, int t) {
#pragma unroll
    for (int m = 0; m < 4; m++) {
        __syncthreads();
        int q    = 1 << (2*m);
        int p    = t & (q - 1);
        int grp  = t >> (2*m);
        int base = grp*(q << 2) + p;
        int ts   = 64 >> (2*m);
        float2 w1 = tw[p*ts];
        float2 w2 = tw[2*p*ts];
        float2 w3 = tw[3*p*ts];
        if (INV) { w1.y = -w1.y; w2.y = -w2.y; w3.y = -w3.y; }
        float2 x0 = s[IDX(base)];
        float2 t1 = cmul(s[IDX(base +   q)], w1);
        float2 t2 = cmul(s[IDX(base + 2*q)], w2);
        float2 t3 = cmul(s[IDX(base + 3*q)], w3);
        float2 b0 = make_float2(x0.x + t2.x, x0.y + t2.y);
        float2 b1 = make_float2(x0.x - t2.x, x0.y - t2.y);
        float2 b2 = make_float2(t1.x + t3.x, t1.y + t3.y);
        float2 b3 = make_float2(t1.x - t3.x, t1.y - t3.y);
        float2 ib3 = INV ? make_float2(-b3.y, b3.x) : make_float2(b3.y, -b3.x);
        s[IDX(base)]        = make_float2(b0.x + b2.x, b0.y + b2.y);
        s[IDX(base +   q)]  = make_float2(b1.x + ib3.x, b1.y + ib3.y);
        s[IDX(base + 2*q)]  = make_float2(b0.x - b2.x, b0.y - b2.y);
        s[IDX(base + 3*q)]  = make_float2(b1.x - ib3.x, b1.y - ib3.y);
    }
    __syncthreads();
}

// S1: FFT along y. block = one row x, 3 channels. Write planar [c][x][y].
__global__ void s1_fft_y(const float* __restrict__ A) {
    __shared__ float2 sm[NC][FSTR];
    __shared__ float2 tw[256];
    int x = blockIdx.x, c = threadIdx.y, t = threadIdx.x;
    int tid = c*64 + t;
    tw_init_smem(tw, tid, 192);
    float2* s = sm[c];
#pragma unroll
    for (int jj = 0; jj < 4; jj++) {
        int i = t + 64*jj;
        s[IDX(rev4(i))] = make_float2(A[(x*NX + i)*NC + c], 0.f);
    }
    fft256_r4<false>(s, tw, t);
#pragma unroll
    for (int jj = 0; jj < 4; jj++) {
        int i = t + 64*jj;
        g_fA[c*NX*NX + x*NX + i] = s[IDX(i)];
    }
}

// S2: FFT along x, 4 ky-columns of one channel per block. grid (64, 3), block (64,4).
__global__ void s2_fft_x() {
    __shared__ float2 sm[4][FSTR];
    __shared__ float2 tw[256];
    int c = blockIdx.y, y0 = blockIdx.x * 4;
    int t = threadIdx.x, yl = threadIdx.y;
    int tid = yl*64 + t;
    tw_init_smem(tw, tid, 256);
    int base = c*NX*NX;
    for (int e = tid; e < 1024; e += 256) {
        int x = e >> 2, yy = e & 3;
        sm[yy][IDX(rev4(x))] = g_fA[base + x*NX + y0 + yy];
    }
    fft256_r4<false>(sm[yl], tw, t);
    for (int e = tid; e < 1024; e += 256) {
        int x = e >> 2, yy = e & 3;
        g_fA[base + x*NX + y0 + yy] = sm[yy][IDX(x)];
    }
}

// S3: multiply by fK + inverse FFT along y. block = one kx row, 4 packed pairs.
// grid (256, 2). H_j = fK_{2j}*fA_{c1} + i*fK_{2j+1}*fA_{c2}.
__global__ void s3_mul_ifft_y(const float* __restrict__ fKr, const float* __restrict__ fKi) {
    __shared__ float2 sm[4][FSTR];
    __shared__ float2 sfA[NC][NX];
    __shared__ float2 tw[256];
    int x = blockIdx.x, t = threadIdx.x, jl = threadIdx.y;
    int j0 = blockIdx.y * 4;
    int tid = jl*64 + t;
    tw_init_smem(tw, tid, 256);
    for (int e = tid; e < NC*NX; e += 256) {
        int c = e >> 8, y = e & 255;
        sfA[c][y] = g_fA[c*NX*NX + x*NX + y];
    }
    __syncthreads();
    for (int e = tid; e < 1024; e += 256) {
        int y = e >> 2, jj = e & 3;
        int k1 = 2*(j0 + jj);
        int idx = (x*NX + y)*NK;
        float2 a1 = sfA[k1 % NC][y];
        float kr = fKr[idx + k1], ki = fKi[idx + k1];
        float2 H = make_float2(kr*a1.x - ki*a1.y, kr*a1.y + ki*a1.x);
        if (k1 + 1 < NK) {
            float2 a2 = sfA[(k1+1) % NC][y];
            float kr2 = fKr[idx + k1 + 1], ki2 = fKi[idx + k1 + 1];
            float zr = kr2*a2.x - ki2*a2.y;
            float zi = kr2*a2.y + ki2*a2.x;
            H.x -= zi; H.y += zr;
        }
        sm[jj][IDX(rev4(y))] = H;
    }
    fft256_r4<true>(sm[jl], tw, t);
    for (int e = tid; e < 1024; e += 256) {
        int y = e >> 2, jj = e & 3;
        g_G[(x*NX + y)*NP + j0 + jj] = sm[jj][IDX(y)];
    }
}

// S4: inverse FFT along x + growth*P + channel-sum, fused. block = one y, 8 pairs.
__global__ void s4_ifft_x_growth(const float* __restrict__ P,
                                 const float* __restrict__ mArr,
                                 const float* __restrict__ sArr) {
    __shared__ float2 sm[NP][FSTR];
    __shared__ float  sP[NX*17];
    __shared__ float2 tw[256];
    int y = blockIdx.x, t = threadIdx.x, j = threadIdx.y;
    int tid = j*64 + t;
    tw_init_smem(tw, tid, 512);
    for (int e = tid; e < 2048; e += 512) {
        int xx = e >> 3, jj = e & 7;
        sm[jj][IDX(rev4(xx))] = g_G[(xx*NX + y)*NP + jj];
    }
    for (int e = tid; e < NX*NK; e += 512) {
        int xx = e / NK, k = e - xx*NK;
        sP[xx*17 + k] = P[(xx*NX + y)*NK + k];
    }
    fft256_r4<true>(sm[j], tw, t);

    int k1 = 2*j, k2 = 2*j + 1;
    float m1 = mArr[k1], s1 = sArr[k1];
    float inv1 = 1.f / (2.f * s1 * s1);
    float m2 = 0.f, inv2 = 0.f;
    if (k2 < NK) { m2 = mArr[k2]; float s2 = sArr[k2]; inv2 = 1.f / (2.f * s2 * s2); }
#pragma unroll
    for (int jj2 = 0; jj2 < 4; jj2++) {
        int xx = t + 64*jj2;
        float2 v = sm[j][IDX(xx)];
        float u1 = v.x * (1.f / 65536.f);
        float d1 = u1 - m1;
        sP[xx*17 + k1] *= (2.f * expf(-d1*d1*inv1) - 1.f);
        if (k2 < NK) {
            float u2 = v.y * (1.f / 65536.f);
            float d2 = u2 - m2;
            sP[xx*17 + k2] *= (2.f * expf(-d2*d2*inv2) - 1.f);
        }
    }
    __syncthreads();
    for (int e = tid; e < NX*NC; e += 512) {
        int xx = e / NC, c = e - xx*NC;
        const float* u = sP + xx*17;
        g_Uc[(y*NX + xx)*NC + c] = u[c] + u[c+3] + u[c+6] + u[c+9] + u[c+12];
    }
}

// Fused sobel + mus + reintegration. Output tile 8(x) x 16(y) per 128-thread block.
// Records: [mu0(3), mu1(3), A(3), P(15)] = 24 floats, 16B-aligned stride.
// Only |shift|<=2 contributes (support 1.15, |DT*F|<=0.87); wrapped/out-of-tile
// sources have exactly-zero area AND zero softmax weight (sentinel mus handles edges).
#define TXo 8
#define TYo 16
__global__ void fused_flow(const float* __restrict__ A, const float* __restrict__ P,
                           float* __restrict__ outA, float* __restrict__ outP) {
    __shared__ __align__(16) float rec[240*24];   // 12 x 20 records
    __shared__ float sUc[14*22*3];
    __shared__ float sAs[14*22];
    int tid = threadIdx.x;                        // 128
    int y0 = blockIdx.x * TYo, x0 = blockIdx.y * TXo;

    // stage 1: Uc + asum staging (14 x 22), zero-padded at image edge
    for (int e = tid; e < 14*22; e += 128) {
        int i = e / 22, j = e - i*22;
        int gx = x0 - 3 + i, gy = y0 - 3 + j;
        float u0 = 0.f, u1 = 0.f, u2 = 0.f, as = 0.f;
        if (gx >= 0 && gx < NX && gy >= 0 && gy < NX) {
            int bU = (gy*NX + gx)*NC;
            u0 = g_Uc[bU]; u1 = g_Uc[bU+1]; u2 = g_Uc[bU+2];
            int bA = (gx*NX + gy)*NC;
            as = A[bA] + A[bA+1] + A[bA+2];
        }
        sUc[e*3+0] = u0; sUc[e*3+1] = u1; sUc[e*3+2] = u2;
        sAs[e] = as;
    }
    __syncthreads();

    // stage 2: sobel + mus + A for 12 x 20 record grid
    for (int e = tid; e < 240; e += 128) {
        int i = e / 20, j = e - i*20;
        int gx = x0 - 2 + i, gy = y0 - 2 + j;
        float* r = rec + e*24;
        if (gx >= 0 && gx < NX && gy >= 0 && gy < NX) {
            int si = i + 1, sj = j + 1;
            int rm = (si-1)*22 + sj, rp = (si+1)*22 + sj, r0 = si*22 + sj;
            float cg0 = (sAs[rp-1] + 2.f*sAs[rp] + sAs[rp+1])
                      - (sAs[rm-1] + 2.f*sAs[rm] + sAs[rm+1]);
            float cg1 = (sAs[rm+1] + 2.f*sAs[r0+1] + sAs[rp+1])
                      - (sAs[rm-1] + 2.f*sAs[r0-1] + sAs[rp-1]);
            int bA = (gx*NX + gy)*NC;
            float p0 = gx + 0.5f, p1 = gy + 0.5f;
#pragma unroll
            for (int c = 0; c < NC; c++) {
                float f0 = (sUc[(rp-1)*3+c] + 2.f*sUc[rp*3+c] + sUc[(rp+1)*3+c])
                         - (sUc[(rm-1)*3+c] + 2.f*sUc[rm*3+c] + sUc[(rm+1)*3+c]);
                float f1 = (sUc[(rm+1)*3+c] + 2.f*sUc[(r0+1)*3+c] + sUc[(rp+1)*3+c])
                         - (sUc[(rm-1)*3+c] + 2.f*sUc[(r0-1)*3+c] + sUc[(rp-1)*3+c]);
                float ac = A[bA + c];
                float ah = ac * 0.5f;
                float alpha = fminf(ah*ah, 1.f);
                float F0 = fminf(fmaxf(f0*(1.f-alpha) - cg0*alpha, -MAc), MAc);
                float F1 = fminf(fmaxf(f1*(1.f-alpha) - cg1*alpha, -MAc), MAc);
                r[c]   = fminf(fmaxf(p0 + DTc*F0, SIGMAc), (float)NX - SIGMAc);
                r[3+c] = fminf(fmaxf(p1 + DTc*F1, SIGMAc), (float)NX - SIGMAc);
                r[6+c] = ac;
            }
        } else {
#pragma unroll
            for (int c = 0; c < 6; c++) r[c] = -1e9f;
            r[6] = r[7] = r[8] = 0.f;
        }
    }
    // stage 2b: P records (k fast -> contiguous global runs)
    for (int e = tid; e < 240*NK; e += 128) {
        int pix = e / NK, k = e - pix*NK;
        int i = pix / 20, j = pix - i*20;
        int gx = x0 - 2 + i, gy = y0 - 2 + j;
        float v = 0.f;
        if (gx >= 0 && gx < NX && gy >= 0 && gy < NX)
            v = P[(gx*NX + gy)*NK + k];
        rec[pix*24 + 9 + k] = v;
    }
    __syncthreads();

    // stage 3: 25-tap gather
    int ty = tid & 15, tx = tid >> 4;
    int x = x0 + tx, y = y0 + ty;
    float p0 = x + 0.5f, p1 = y + 0.5f;
    float accA0 = 0.f, accA1 = 0.f, accA2 = 0.f, accW = 0.f;
    float accP[NK];
#pragma unroll
    for (int k = 0; k < NK; k++) accP[k] = 0.f;

#pragma unroll
    for (int dx = -2; dx <= 2; dx++) {
#pragma unroll
        for (int dy = -2; dy <= 2; dy++) {
            int ridx = (tx + 2 - dx)*20 + (ty + 2 - dy);
            const float4* r4 = (const float4*)(rec + ridx*24);
            float4 q0 = r4[0];   // mu00 mu01 mu02 mu10
            float4 q1 = r4[1];   // mu11 mu12 A0 A1
            float4 q2 = r4[2];   // A2 P0 P1 P2
            float s00 = fminf(fmaxf(SUPP - fabsf(p0 - q0.x), 0.f), 1.f);
            float s01 = fminf(fmaxf(SUPP - fabsf(p0 - q0.y), 0.f), 1.f);
            float s02 = fminf(fmaxf(SUPP - fabsf(p0 - q0.z), 0.f), 1.f);
            float s10 = fminf(fmaxf(SUPP - fabsf(p1 - q0.w), 0.f), 1.f);
            float s11 = fminf(fmaxf(SUPP - fabsf(p1 - q1.x), 0.f), 1.f);
            float s12 = fminf(fmaxf(SUPP - fabsf(p1 - q1.y), 0.f), 1.f);
            float v0 = q1.z * (s00*s10*INV4S2);
            float v1 = q1.w * (s01*s11*INV4S2);
            float v2 = q2.x * (s02*s12*INV4S2);
            accA0 += v0; accA1 += v1; accA2 += v2;
            float suma = v0 + v1 + v2;
            if (suma > 0.f) {
                float w = expf(suma) - 1.f;
                accW += w;
                accP[0] += w*q2.y; accP[1] += w*q2.z; accP[2] += w*q2.w;
                float4 q3 = r4[3], q4 = r4[4], q5 = r4[5];
                accP[3] += w*q3.x; accP[4] += w*q3.y; accP[5] += w*q3.z; accP[6] += w*q3.w;
                accP[7] += w*q4.x; accP[8] += w*q4.y; accP[9] += w*q4.z; accP[10] += w*q4.w;
                accP[11] += w*q5.x; accP[12] += w*q5.y; accP[13] += w*q5.z; accP[14] += w*q5.w;
            }
        }
    }

    int o = x*NX + y;
    outA[o*NC + 0] = accA0; outA[o*NC + 1] = accA1; outA[o*NC + 2] = accA2;
    float inv = 1.f / (accW + 1e-10f);
#pragma unroll
    for (int k = 0; k < NK; k++) outP[o*NK + k] = accP[k] * inv;
}

extern "C" void kernel_launch(void* const* d_in, const int* in_sizes, int n_in,
                              void* d_out, int out_size) {
    const float* A   = (const float*)d_in[0];
    const float* P   = (const float*)d_in[1];
    const float* fKr = (const float*)d_in[2];
    const float* fKi = (const float*)d_in[3];
    const float* m   = (const float*)d_in[4];
    const float* s   = (const float*)d_in[5];
    float* outA = (float*)d_out;
    float* outP = outA + NX*NX*NC;

    s1_fft_y         <<<NX, dim3(64, NC)>>>(A);
    s2_fft_x         <<<dim3(64, NC), dim3(64, 4)>>>();
    s3_mul_ifft_y    <<<dim3(NX, 2), dim3(64, 4)>>>(fKr, fKi);
    s4_ifft_x_growth <<<NX, dim3(64, NP)>>>(P, m, s);
    fused_flow       <<<dim3(16, 32), 128>>>(A, P, outA, outP);
}